// round 16
// baseline (speedup 1.0000x reference)
#include <cuda_runtime.h>
#include <cuda_fp16.h>
#include <cstdint>

// Problem constants
#define PB 4
#define PS 2048
#define PD 512
#define PH 8
#define HD 64
#define BH (PB*PH)          // 32
#define PM (PB*PS)          // 8192

// Scratch (device globals; no allocations allowed)
__device__ __half g_qin[PM * PD];        // query in fp16
__device__ __half g_vin[PM * PD];        // value in fp16
__device__ __half g_wT[3 * PD * PD];     // [Wq^T | Wk^T | Wv^T] fp16, [n][k]
__device__ __half g_woT[PD * PD];        // Wo^T fp16 [n][k]
__device__ __half g_q[BH * PS * HD];     // [bh][s][d] fp16, pre-scaled by normalizer*log2e
__device__ __half g_k[BH * PS * HD];     // [bh][s][d] fp16
__device__ __half g_v[BH * PS * HD];     // [bh][s][d] fp16
__device__ float  g_heads[PB * PS * PD]; // [b][s][h*64+hd] fp32
__device__ __half g_normh[PM * PD];      // normalized heads fp16

// ---------------------------------------------------------------------------
// helpers
// ---------------------------------------------------------------------------
__device__ __forceinline__ uint32_t smem_u32(const void* p) {
    uint32_t a;
    asm("{ .reg .u64 t; cvta.to.shared.u64 t, %1; cvt.u32.u64 %0, t; }"
        : "=r"(a) : "l"(p));
    return a;
}

__device__ __forceinline__ float fexp2(float x) {
    float y;
    asm("ex2.approx.f32 %0, %1;" : "=f"(y) : "f"(x));
    return y;
}

__device__ __forceinline__ uint32_t hexp2(uint32_t x) {
    uint32_t y;
    asm("ex2.approx.f16x2 %0, %1;" : "=r"(y) : "r"(x));
    return y;
}

#define SW128(off) ((off) ^ (((off) >> 3) & 0x70))

#define CP16(dst, src) \
    asm volatile("cp.async.cg.shared.global [%0], [%1], 16;" \
                 :: "r"((uint32_t)(dst)), "l"(src))
#define CP_COMMIT() asm volatile("cp.async.commit_group;" ::: "memory")
#define CP_WAIT(n)  asm volatile("cp.async.wait_group %0;" :: "n"(n) : "memory")

#define LDSM_X4(r0, r1, r2, r3, addr) \
    asm volatile("ldmatrix.sync.aligned.m8n8.x4.shared.b16 {%0,%1,%2,%3}, [%4];" \
                 : "=r"(r0), "=r"(r1), "=r"(r2), "=r"(r3) : "r"(addr))
#define LDSM_X4_T(r0, r1, r2, r3, addr) \
    asm volatile("ldmatrix.sync.aligned.m8n8.x4.trans.shared.b16 {%0,%1,%2,%3}, [%4];" \
                 : "=r"(r0), "=r"(r1), "=r"(r2), "=r"(r3) : "r"(addr))

__device__ __forceinline__ void mma_f16(float c[4], uint32_t a0, uint32_t a1,
                                        uint32_t a2, uint32_t a3,
                                        uint32_t b0, uint32_t b1) {
    asm volatile(
        "mma.sync.aligned.m16n8k16.row.col.f32.f16.f16.f32 "
        "{%0,%1,%2,%3}, {%4,%5,%6,%7}, {%8,%9}, {%0,%1,%2,%3};\n"
        : "+f"(c[0]), "+f"(c[1]), "+f"(c[2]), "+f"(c[3])
        : "r"(a0), "r"(a1), "r"(a2), "r"(a3), "r"(b0), "r"(b1));
}

// ---------------------------------------------------------------------------
// Fused prep: blocks 0-2047 convert query/value to fp16 (4 float4/thread,
// MLP=4); blocks 2048+ transpose weights to fp16 K-major.
// ---------------------------------------------------------------------------
__global__ void __launch_bounds__(256)
prep(const float* __restrict__ query, const float* __restrict__ value,
     const float* __restrict__ Wq, const float* __restrict__ Wkv,
     const float* __restrict__ Wo)
{
    const int bx = blockIdx.x;
    if (bx < 2048) {
        const float* src = (bx < 1024) ? query : value;
        __half* dst = (bx < 1024) ? g_qin : g_vin;
        size_t base = (size_t)(bx & 1023) * 4096 + threadIdx.x * 4;
        #pragma unroll
        for (int l = 0; l < 4; l++) {
            size_t off = base + l * 1024;
            float4 v = *(const float4*)(src + off);
            __half2 h0 = __floats2half2_rn(v.x, v.y);
            __half2 h1 = __floats2half2_rn(v.z, v.w);
            *(uint2*)(dst + off) = make_uint2(*(uint32_t*)&h0, *(uint32_t*)&h1);
        }
        return;
    }
    __shared__ float t[32][33];
    int tt = bx - 2048;
    const float* src; __half* dst; int Nd, bn, bk;
    if (tt < 256)      { src = Wq;  dst = g_wT;           Nd = 512;  bn = (tt & 15) * 32; bk = (tt >> 4) * 32; }
    else if (tt < 768) { int u = tt - 256;
                         src = Wkv; dst = g_wT + PD * PD; Nd = 1024; bn = (u & 31) * 32;  bk = (u >> 5) * 32; }
    else               { int u = tt - 768;
                         src = Wo;  dst = g_woT;          Nd = 512;  bn = (u & 15) * 32;  bk = (u >> 4) * 32; }
    int tx = threadIdx.x & 31, ty = threadIdx.x >> 5;
    #pragma unroll
    for (int j = 0; j < 32; j += 8)
        t[ty + j][tx] = src[(size_t)(bk + ty + j) * Nd + bn + tx];
    __syncthreads();
    #pragma unroll
    for (int j = 0; j < 32; j += 8)
        dst[(size_t)(bn + ty + j) * PD + bk + tx] = __float2half(t[tx][ty + j]);
}

// ---------------------------------------------------------------------------
// QKV GEMM: 64x128 CTA tile, warp grid 2m x 4n (warp tile 32x32),
// 3 CTAs/SM. K=512 in 8 chunks, 3-stage cp.async pipeline (24KB/stage).
// bx: 0-3 Q, 4-7 K, 8-11 V. Epilogue -> g_q (scaled) / g_k / g_v.
// ---------------------------------------------------------------------------
__global__ void __launch_bounds__(256, 3)
gemm_qkv(const __half* __restrict__ Aq, const __half* __restrict__ Av,
         const __half* __restrict__ W, const float* __restrict__ normPtr)
{
    extern __shared__ char dsm[];
    uint32_t raw = smem_u32(dsm);
    uint32_t sb = (raw + 1023u) & ~1023u;

    const int tid = threadIdx.x, warp = tid >> 5, lane = tid & 31;
    const int wm = warp & 1, wn = warp >> 1;       // 2m x 4n
    const int lq = lane >> 2, lr = lane & 3;
    const int bx = blockIdx.x;
    const int m0 = blockIdx.y * 64;
    const int n0 = bx * 128;
    const int sector = bx >> 2;

    const __half* A = (sector == 0) ? Aq : Av;

    float acc[2][4][4];
    #pragma unroll
    for (int mi = 0; mi < 2; mi++)
        #pragma unroll
        for (int nj = 0; nj < 4; nj++)
            #pragma unroll
            for (int j = 0; j < 4; j++) acc[mi][nj][j] = 0.f;

    auto load_chunk = [&](int i) {
        const int k0 = i * 64;
        const uint32_t dA = sb + (i % 3) * 24576;
        const uint32_t dB = dA + 8192;
        #pragma unroll
        for (int l = 0; l < 2; l++) {
            int idx = tid + l * 256;
            int r = idx >> 3, c = (idx & 7) * 8;
            CP16(dA + SW128(r * 128 + c * 2), A + (size_t)(m0 + r) * PD + k0 + c);
        }
        #pragma unroll
        for (int l = 0; l < 4; l++) {
            int idx = tid + l * 256;
            int r = idx >> 3, c = (idx & 7) * 8;
            CP16(dB + SW128(r * 128 + c * 2), W + (size_t)(n0 + r) * PD + k0 + c);
        }
        CP_COMMIT();
    };

    load_chunk(0);
    load_chunk(1);

    #pragma unroll 1
    for (int i = 0; i < 8; i++) {
        if (i == 7) { CP_WAIT(0); }
        else        { CP_WAIT(1); }
        __syncthreads();
        if (i + 2 < 8) load_chunk(i + 2);  // buf (i+2)%3 == (i-1)%3: safe after sync

        const uint32_t Ab = sb + (i % 3) * 24576;
        const uint32_t Bb = Ab + 8192;
        #pragma unroll
        for (int ks = 0; ks < 4; ks++) {
            const int kh = ks * 16 + (lane >> 4) * 8;
            uint32_t a[2][4];
            #pragma unroll
            for (int mi = 0; mi < 2; mi++) {
                int row = wm * 32 + mi * 16 + (lane & 15);
                LDSM_X4(a[mi][0], a[mi][1], a[mi][2], a[mi][3],
                        Ab + SW128(row * 128 + kh * 2));
            }
            #pragma unroll
            for (int nj2 = 0; nj2 < 2; nj2++) {
                uint32_t r0, r1, r2, r3;
                int row = wn * 32 + nj2 * 16 + (lane & 15);
                LDSM_X4(r0, r1, r2, r3, Bb + SW128(row * 128 + kh * 2));
                #pragma unroll
                for (int mi = 0; mi < 2; mi++) {
                    mma_f16(acc[mi][2 * nj2],     a[mi][0], a[mi][1], a[mi][2], a[mi][3], r0, r2);
                    mma_f16(acc[mi][2 * nj2 + 1], a[mi][0], a[mi][1], a[mi][2], a[mi][3], r1, r3);
                }
            }
        }
    }

    // Epilogue: Q gets normalizer * log2(e) so flash can use exp2 directly
    const float scale = (sector == 0) ? (*normPtr * 1.4426950408889634f) : 1.f;
    __half* dst = (sector == 0) ? g_q : ((sector == 1) ? g_k : g_v);
    #pragma unroll
    for (int mi = 0; mi < 2; mi++)
        #pragma unroll
        for (int rr = 0; rr < 2; rr++) {
            int m = m0 + wm * 32 + mi * 16 + lq + rr * 8;
            int b = m >> 11, s = m & 2047;
            #pragma unroll
            for (int nj = 0; nj < 4; nj++) {
                int nn = (bx & 3) * 128 + wn * 32 + nj * 8 + 2 * lr;
                int h = nn >> 6, d = nn & 63;
                __half2 hv = __floats2half2_rn(acc[mi][nj][rr * 2] * scale,
                                               acc[mi][nj][rr * 2 + 1] * scale);
                *(__half2*)(dst + (((size_t)(b * PH + h)) * PS + s) * HD + d) = hv;
            }
        }
}

// ---------------------------------------------------------------------------
// Output GEMM: 128x128 CTA tile (256 CTAs = single wave), K=512 in 8 chunks,
// 3-stage cp.async pipeline, ldmatrix + m16n8k16 f32-acc. -> fp32 C.
// ---------------------------------------------------------------------------
__global__ void __launch_bounds__(256, 2)
gemm_out(const __half* __restrict__ Ain, const __half* __restrict__ W,
         float* __restrict__ C)
{
    extern __shared__ char dsm[];
    uint32_t raw = smem_u32(dsm);
    uint32_t sb = (raw + 1023u) & ~1023u;

    const int tid = threadIdx.x, warp = tid >> 5, lane = tid & 31;
    const int wm = warp & 3, wn = warp >> 2;
    const int lq = lane >> 2, lr = lane & 3;
    const int m0 = blockIdx.y * 128;
    const int n0 = blockIdx.x * 128;

    float acc[2][8][4];
    #pragma unroll
    for (int mi = 0; mi < 2; mi++)
        #pragma unroll
        for (int ni = 0; ni < 8; ni++)
            #pragma unroll
            for (int j = 0; j < 4; j++) acc[mi][ni][j] = 0.f;

    auto load_chunk = [&](int i) {
        const int k0 = i * 64;
        const uint32_t dA = sb + (i % 3) * 32768;
        const uint32_t dB = dA + 16384;
        #pragma unroll
        for (int l = 0; l < 4; l++) {
            int idx = tid + l * 256;
            int r = idx >> 3, c = (idx & 7) * 8;
            CP16(dA + SW128(r * 128 + c * 2), Ain + (size_t)(m0 + r) * PD + k0 + c);
            CP16(dB + SW128(r * 128 + c * 2), W + (size_t)(n0 + r) * PD + k0 + c);
        }
        CP_COMMIT();
    };

    load_chunk(0);
    load_chunk(1);

    #pragma unroll 1
    for (int i = 0; i < 8; i++) {
        if (i == 7) { CP_WAIT(0); }
        else        { CP_WAIT(1); }
        __syncthreads();
        if (i + 2 < 8) load_chunk(i + 2);

        const uint32_t Ab = sb + (i % 3) * 32768;
        const uint32_t Bb = Ab + 16384;
        #pragma unroll
        for (int ks = 0; ks < 4; ks++) {
            const int kh = ks * 16 + (lane >> 4) * 8;
            uint32_t a[2][4];
            #pragma unroll
            for (int mi = 0; mi < 2; mi++) {
                int row = wm * 32 + mi * 16 + (lane & 15);
                LDSM_X4(a[mi][0], a[mi][1], a[mi][2], a[mi][3],
                        Ab + SW128(row * 128 + kh * 2));
            }
            #pragma unroll
            for (int np = 0; np < 4; np++) {
                uint32_t r0, r1, r2, r3;
                int row = wn * 64 + np * 16 + (lane & 15);
                LDSM_X4(r0, r1, r2, r3, Bb + SW128(row * 128 + kh * 2));
                #pragma unroll
                for (int mi = 0; mi < 2; mi++) {
                    mma_f16(acc[mi][2 * np],     a[mi][0], a[mi][1], a[mi][2], a[mi][3], r0, r2);
                    mma_f16(acc[mi][2 * np + 1], a[mi][0], a[mi][1], a[mi][2], a[mi][3], r1, r3);
                }
            }
        }
    }

    #pragma unroll
    for (int mi = 0; mi < 2; mi++)
        #pragma unroll
        for (int rr = 0; rr < 2; rr++) {
            int m = m0 + wm * 32 + mi * 16 + lq + rr * 8;
            #pragma unroll
            for (int ni = 0; ni < 8; ni++) {
                int c = n0 + wn * 64 + ni * 8 + 2 * lr;
                *(float2*)(C + (size_t)m * PD + c) =
                    make_float2(acc[mi][ni][rr * 2], acc[mi][ni][rr * 2 + 1]);
            }
        }
}

// ---------------------------------------------------------------------------
// fp16 flash attention: 128 q-rows, KV in 128-wide pairs, 8 warps, register-
// fused P, ballot-guarded alpha rescale, LPT grid. li now via SCALAR fp32
// sums of the fp16 P fragments (removes 4 HMMA/sub-tile from the tensor
// pipe; sums the same fp16 values, so same quantization level). Causal.
// ---------------------------------------------------------------------------
__global__ void __launch_bounds__(256, 2)
flash_h()
{
    extern __shared__ char dsm[];
    uint32_t raw = smem_u32(dsm);
    uint32_t sb = (raw + 1023u) & ~1023u;
    const uint32_t Qs = sb;  // 16KB [r][d]
    // pair buffer b at sb+16384+b*32768: K(128 kv rows) 16KB, V 16KB

    const int bh = blockIdx.x;                            // 0..31
    const int qt = (int)gridDim.y - 1 - (int)blockIdx.y;  // heavy tiles first (LPT)
    const int qbase = qt * 128;

    const int tid = threadIdx.x, warp = tid >> 5, lane = tid & 31;
    const int lq = lane >> 2, lr = lane & 3;
    const int wrow = warp * 16;

    const __half* qp = g_q + (size_t)bh * PS * HD;
    const __half* kp = g_k + (size_t)bh * PS * HD;
    const __half* vp = g_v + (size_t)bh * PS * HD;

    auto load_pair = [&](int p) {   // loads K/V rows [p*128, p*128+128)
        const int kb = p * 128;
        const uint32_t base = sb + 16384 + (p & 1) * 32768;
        #pragma unroll
        for (int l = 0; l < 4; l++) {
            int idx = tid + l * 256;
            int r = idx >> 3, c = (idx & 7) * 8;
            CP16(base + SW128(r * 128 + c * 2),         kp + (size_t)(kb + r) * HD + c);
            CP16(base + 16384 + SW128(r * 128 + c * 2), vp + (size_t)(kb + r) * HD + c);
        }
        CP_COMMIT();
    };

    const int pairs = qt + 1;

    // Q tile + pair 0 in one commit group
    #pragma unroll
    for (int l = 0; l < 4; l++) {
        int idx = tid + l * 256;
        int r = idx >> 3, c = (idx & 7) * 8;
        CP16(Qs + SW128(r * 128 + c * 2), qp + (size_t)(qbase + r) * HD + c);
    }
    load_pair(0);

    CP_WAIT(0);
    __syncthreads();

    // Hoist Q fragments (warp-invariant across kv tiles): 16 regs
    uint32_t qf[4][4];
    #pragma unroll
    for (int ks = 0; ks < 4; ks++) {
        const int kh = ks * 16 + (lane >> 4) * 8;
        LDSM_X4(qf[ks][0], qf[ks][1], qf[ks][2], qf[ks][3],
                Qs + SW128((wrow + (lane & 15)) * 128 + kh * 2));
    }

    float mi2[2] = {-1e30f, -1e30f};
    float li2[2] = {0.f, 0.f};   // row sums (fp32)
    float o[8][4];
    #pragma unroll
    for (int ni = 0; ni < 8; ni++)
        #pragma unroll
        for (int j = 0; j < 4; j++) o[ni][j] = 0.f;

    // one 64-kv sub-tile (kb = global kv base; Kb/Vb = smem bases, row-local)
    auto process_tile = [&](int kb, uint32_t Kb, uint32_t Vb) {
        // Skip warp-tiles entirely above the diagonal
        if (kb > qbase + wrow + 15) return;

        // ---- S = Q K^T ----
        float s[8][4];
        #pragma unroll
        for (int ni = 0; ni < 8; ni++)
            #pragma unroll
            for (int j = 0; j < 4; j++) s[ni][j] = 0.f;

        #pragma unroll
        for (int ks = 0; ks < 4; ks++) {
            const int kh = ks * 16 + (lane >> 4) * 8;
            #pragma unroll
            for (int np = 0; np < 4; np++) {
                uint32_t r0, r1, r2, r3;
                LDSM_X4(r0, r1, r2, r3,
                        Kb + SW128((np * 16 + (lane & 15)) * 128 + kh * 2));
                mma_f16(s[2 * np],     qf[ks][0], qf[ks][1], qf[ks][2], qf[ks][3], r0, r2);
                mma_f16(s[2 * np + 1], qf[ks][0], qf[ks][1], qf[ks][2], qf[ks][3], r1, r3);
            }
        }

        // Causal mask (only near the diagonal)
        if (kb + 63 > qbase + wrow) {
            #pragma unroll
            for (int ni = 0; ni < 8; ni++)
                #pragma unroll
                for (int j = 0; j < 4; j++) {
                    int col = kb + ni * 8 + 2 * lr + (j & 1);
                    int row = qbase + wrow + lq + ((j >> 1) << 3);
                    if (col > row) s[ni][j] = -1e30f;
                }
        }

        // Row max (fp32, quad reduce)
        float mn[2];
        #pragma unroll
        for (int rr = 0; rr < 2; rr++) {
            float mx = -1e30f;
            #pragma unroll
            for (int ni = 0; ni < 8; ni++)
                mx = fmaxf(mx, fmaxf(s[ni][rr * 2], s[ni][rr * 2 + 1]));
            mx = fmaxf(mx, __shfl_xor_sync(0xffffffffu, mx, 1));
            mx = fmaxf(mx, __shfl_xor_sync(0xffffffffu, mx, 2));
            mn[rr] = fmaxf(mi2[rr], mx);
        }

        // Ballot-guarded rescale: skipped only when alpha==1.0 exactly.
        bool adv = (mn[0] > mi2[0]) | (mn[1] > mi2[1]);
        if (__ballot_sync(0xffffffffu, adv)) {
            float a0 = fexp2(mi2[0] - mn[0]);
            float a1 = fexp2(mi2[1] - mn[1]);
            #pragma unroll
            for (int ni = 0; ni < 8; ni++) {
                o[ni][0] *= a0; o[ni][1] *= a0;
                o[ni][2] *= a1; o[ni][3] *= a1;
            }
            li2[0] *= a0;
            li2[1] *= a1;
            mi2[0] = mn[0];
            mi2[1] = mn[1];
        }

        // P = exp2(S - mn): subtract in fp32, convert, ex2.f16x2
        uint32_t ph[8][2];
        #pragma unroll
        for (int ni = 0; ni < 8; ni++) {
            __half2 h0 = __floats2half2_rn(s[ni][0] - mn[0], s[ni][1] - mn[0]);
            __half2 h1 = __floats2half2_rn(s[ni][2] - mn[1], s[ni][3] - mn[1]);
            ph[ni][0] = hexp2(*(uint32_t*)&h0);
            ph[ni][1] = hexp2(*(uint32_t*)&h1);
        }

        // li += row-sum of fp16 P, summed in fp32 on the scalar pipes
        // (frees 4 HMMA/sub-tile from the tensor pipe)
        {
            float s0 = 0.f, s1 = 0.f;
            #pragma unroll
            for (int ni = 0; ni < 8; ni++) {
                float2 f0 = __half22float2(*(__half2*)&ph[ni][0]);
                float2 f1 = __half22float2(*(__half2*)&ph[ni][1]);
                s0 += f0.x + f0.y;
                s1 += f1.x + f1.y;
            }
            s0 += __shfl_xor_sync(0xffffffffu, s0, 1);
            s0 += __shfl_xor_sync(0xffffffffu, s0, 2);
            s1 += __shfl_xor_sync(0xffffffffu, s1, 1);
            s1 += __shfl_xor_sync(0xffffffffu, s1, 2);
            li2[0] += s0;
            li2[1] += s1;
        }

        // ---- O += P V ----
        #pragma unroll
        for (int ks = 0; ks < 4; ks++) {
            #pragma unroll
            for (int dt = 0; dt < 4; dt++) {
                int kvr = ks * 16 + ((lane >> 3) & 1) * 8 + (lane & 7);
                int dof = dt * 16 + (lane >> 4) * 8;
                uint32_t r0, r1, r2, r3;
                LDSM_X4_T(r0, r1, r2, r3, Vb + SW128(kvr * 128 + dof * 2));
                mma_f16(o[dt * 2],     ph[2 * ks][0], ph[2 * ks][1],
                        ph[2 * ks + 1][0], ph[2 * ks + 1][1], r0, r1);
                mma_f16(o[dt * 2 + 1], ph[2 * ks][0], ph[2 * ks][1],
                        ph[2 * ks + 1][0], ph[2 * ks + 1][1], r2, r3);
            }
        }
    };

    #pragma unroll 1
    for (int p = 0; p < pairs; p++) {
        if (p > 0) {
            CP_WAIT(0);       // exactly pair p pending -> exact wait
            __syncthreads();
        }
        if (p + 1 < pairs) load_pair(p + 1);  // other buffer; in flight during processing

        const uint32_t base = sb + 16384 + (p & 1) * 32768;
        process_tile(p * 128,      base,        base + 16384);
        process_tile(p * 128 + 64, base + 8192, base + 16384 + 8192);
    }

    // Epilogue: g_heads[b][row][h*64+d] fp32
    const int b = bh >> 3, h = bh & 7;
    #pragma unroll
    for (int rr = 0; rr < 2; rr++) {
        float inv = 1.f / li2[rr];
        int row = qbase + wrow + lq + rr * 8;
        #pragma unroll
        for (int ni = 0; ni < 8; ni++) {
            size_t off = ((size_t)b * PS + row) * PD + h * HD + ni * 8 + 2 * lr;
            *(float2*)(g_heads + off) =
                make_float2(o[ni][rr * 2] * inv, o[ni][rr * 2 + 1] * inv);
        }
    }
}

// ---------------------------------------------------------------------------
// Cross-head normalization (fp32 math, float2/thread)
// ---------------------------------------------------------------------------
__global__ void __launch_bounds__(256)
norm_k(const float* __restrict__ head_mults)
{
    int i = (blockIdx.x * 256 + threadIdx.x) * 2;  // over B*S*64, 2 hd/thread
    int hd = i & 63;
    int bs = i >> 6;
    size_t base = (size_t)bs * PD + hd;

    float2 v[PH];
    float2 mean = make_float2(0.f, 0.f);
    #pragma unroll
    for (int h = 0; h < PH; h++) {
        v[h] = *(const float2*)(g_heads + base + h * HD);
        mean.x += v[h].x; mean.y += v[h].y;
    }
    mean.x *= 0.125f; mean.y *= 0.125f;
    float2 var = make_float2(0.f, 0.f);
    #pragma unroll
    for (int h = 0; h < PH; h++) {
        float dx = v[h].x - mean.x, dy = v[h].y - mean.y;
        var.x += dx * dx; var.y += dy * dy;
    }
    float ix = 1.f / (sqrtf(var.x * 0.125f) + 0.01f);
    float iy = 1.f / (sqrtf(var.y * 0.125f) + 0.01f);
    #pragma unroll
    for (int h = 0; h < PH; h++) {
        float hm = head_mults[h];
        __half2 h0 = __floats2half2_rn((v[h].x - mean.x) * ix * hm,
                                       (v[h].y - mean.y) * iy * hm);
        *(uint32_t*)(g_normh + base + h * HD) = *(uint32_t*)&h0;
    }
}

// ---------------------------------------------------------------------------
// kernel_launch
// ---------------------------------------------------------------------------
extern "C" void kernel_launch(void* const* d_in, const int* in_sizes, int n_in,
                              void* d_out, int out_size)
{
    const float* query      = (const float*)d_in[0];
    const float* value      = (const float*)d_in[1];
    // d_in[2] = mask: pure causal additive mask, implemented analytically
    const float* Wq         = (const float*)d_in[3];
    const float* Wkv        = (const float*)d_in[4];
    const float* Wo         = (const float*)d_in[5];
    const float* normalizer = (const float*)d_in[6];
    const float* head_mults = (const float*)d_in[7];
    float* out = (float*)d_out;

    const int QKV_SMEM   = 3 * 24576 + 1024;          // 74752 -> 3 CTAs/SM
    const int OUT_SMEM   = 3 * 32768 + 1024;          // 99328 -> 2 CTAs/SM
    const int FLASH_SMEM = 16384 + 2 * 32768 + 1024;  // 83968 -> 2 CTAs/SM
    cudaFuncSetAttribute(gemm_qkv, cudaFuncAttributeMaxDynamicSharedMemorySize, QKV_SMEM);
    cudaFuncSetAttribute(gemm_out, cudaFuncAttributeMaxDynamicSharedMemorySize, OUT_SMEM);
    cudaFuncSetAttribute(flash_h,  cudaFuncAttributeMaxDynamicSharedMemorySize, FLASH_SMEM);

    __half *qin, *vin, *wT, *woT, *normh;
    cudaGetSymbolAddress((void**)&qin,   g_qin);
    cudaGetSymbolAddress((void**)&vin,   g_vin);
    cudaGetSymbolAddress((void**)&wT,    g_wT);
    cudaGetSymbolAddress((void**)&woT,   g_woT);
    cudaGetSymbolAddress((void**)&normh, g_normh);

    // 0. Fused prep: fp16 conversion of activations + weight transposes
    prep<<<2048 + 1024, 256>>>(query, value, Wq, Wkv, Wo);

    // 1. Fused QKV projection (64x128 tiles, 2m x 4n warps, 3 CTAs/SM)
    gemm_qkv<<<dim3(12, PM / 64), 256, QKV_SMEM>>>(qin, vin, wT, normalizer);

    // 2. Causal flash attention -> g_heads (fp32); grid (bh, qtile) = LPT order
    flash_h<<<dim3(BH, PS / 128), 256, FLASH_SMEM>>>();

    // 3. Cross-head normalization -> g_normh (fp16)
    norm_k<<<PB * PS * HD / 512, 256>>>(head_mults);

    // 4. Output projection -> d_out (fp32); 256 CTAs = single wave
    gemm_out<<<dim3(4, PM / 128), 256, OUT_SMEM>>>(normh, woT, out);
}

// round 17
// speedup vs baseline: 1.0177x; 1.0177x over previous
#include <cuda_runtime.h>
#include <cuda_fp16.h>
#include <cstdint>

// Problem constants
#define PB 4
#define PS 2048
#define PD 512
#define PH 8
#define HD 64
#define BH (PB*PH)          // 32
#define PM (PB*PS)          // 8192

// Scratch (device globals; no allocations allowed)
__device__ __half g_qin[PM * PD];        // query in fp16
__device__ __half g_vin[PM * PD];        // value in fp16
__device__ __half g_wT[3 * PD * PD];     // [Wq^T | Wk^T | Wv^T] fp16, [n][k]
__device__ __half g_woT[PD * PD];        // Wo^T fp16 [n][k]
__device__ __half g_q[BH * PS * HD];     // [bh][s][d] fp16, pre-scaled by normalizer*log2e
__device__ __half g_k[BH * PS * HD];     // [bh][s][d] fp16
__device__ __half g_v[BH * PS * HD];     // [bh][s][d] fp16
__device__ float  g_heads[PB * PS * PD]; // [b][s][h*64+hd] fp32
__device__ __half g_normh[PM * PD];      // normalized heads fp16

// ---------------------------------------------------------------------------
// helpers
// ---------------------------------------------------------------------------
__device__ __forceinline__ uint32_t smem_u32(const void* p) {
    uint32_t a;
    asm("{ .reg .u64 t; cvta.to.shared.u64 t, %1; cvt.u32.u64 %0, t; }"
        : "=r"(a) : "l"(p));
    return a;
}

__device__ __forceinline__ float fexp2(float x) {
    float y;
    asm("ex2.approx.f32 %0, %1;" : "=f"(y) : "f"(x));
    return y;
}

__device__ __forceinline__ uint32_t hexp2(uint32_t x) {
    uint32_t y;
    asm("ex2.approx.f16x2 %0, %1;" : "=r"(y) : "r"(x));
    return y;
}

#define SW128(off) ((off) ^ (((off) >> 3) & 0x70))

#define CP16(dst, src) \
    asm volatile("cp.async.cg.shared.global [%0], [%1], 16;" \
                 :: "r"((uint32_t)(dst)), "l"(src))
#define CP_COMMIT() asm volatile("cp.async.commit_group;" ::: "memory")
#define CP_WAIT(n)  asm volatile("cp.async.wait_group %0;" :: "n"(n) : "memory")

#define LDSM_X4(r0, r1, r2, r3, addr) \
    asm volatile("ldmatrix.sync.aligned.m8n8.x4.shared.b16 {%0,%1,%2,%3}, [%4];" \
                 : "=r"(r0), "=r"(r1), "=r"(r2), "=r"(r3) : "r"(addr))
#define LDSM_X4_T(r0, r1, r2, r3, addr) \
    asm volatile("ldmatrix.sync.aligned.m8n8.x4.trans.shared.b16 {%0,%1,%2,%3}, [%4];" \
                 : "=r"(r0), "=r"(r1), "=r"(r2), "=r"(r3) : "r"(addr))

__device__ __forceinline__ void mma_f16(float c[4], uint32_t a0, uint32_t a1,
                                        uint32_t a2, uint32_t a3,
                                        uint32_t b0, uint32_t b1) {
    asm volatile(
        "mma.sync.aligned.m16n8k16.row.col.f32.f16.f16.f32 "
        "{%0,%1,%2,%3}, {%4,%5,%6,%7}, {%8,%9}, {%0,%1,%2,%3};\n"
        : "+f"(c[0]), "+f"(c[1]), "+f"(c[2]), "+f"(c[3])
        : "r"(a0), "r"(a1), "r"(a2), "r"(a3), "r"(b0), "r"(b1));
}

// ---------------------------------------------------------------------------
// Fused prep: blocks 0-2047 convert query/value to fp16 (4 float4/thread,
// MLP=4); blocks 2048+ transpose weights to fp16 K-major.
// ---------------------------------------------------------------------------
__global__ void __launch_bounds__(256)
prep(const float* __restrict__ query, const float* __restrict__ value,
     const float* __restrict__ Wq, const float* __restrict__ Wkv,
     const float* __restrict__ Wo)
{
    const int bx = blockIdx.x;
    if (bx < 2048) {
        const float* src = (bx < 1024) ? query : value;
        __half* dst = (bx < 1024) ? g_qin : g_vin;
        size_t base = (size_t)(bx & 1023) * 4096 + threadIdx.x * 4;
        #pragma unroll
        for (int l = 0; l < 4; l++) {
            size_t off = base + l * 1024;
            float4 v = *(const float4*)(src + off);
            __half2 h0 = __floats2half2_rn(v.x, v.y);
            __half2 h1 = __floats2half2_rn(v.z, v.w);
            *(uint2*)(dst + off) = make_uint2(*(uint32_t*)&h0, *(uint32_t*)&h1);
        }
        return;
    }
    __shared__ float t[32][33];
    int tt = bx - 2048;
    const float* src; __half* dst; int Nd, bn, bk;
    if (tt < 256)      { src = Wq;  dst = g_wT;           Nd = 512;  bn = (tt & 15) * 32; bk = (tt >> 4) * 32; }
    else if (tt < 768) { int u = tt - 256;
                         src = Wkv; dst = g_wT + PD * PD; Nd = 1024; bn = (u & 31) * 32;  bk = (u >> 5) * 32; }
    else               { int u = tt - 768;
                         src = Wo;  dst = g_woT;          Nd = 512;  bn = (u & 15) * 32;  bk = (u >> 4) * 32; }
    int tx = threadIdx.x & 31, ty = threadIdx.x >> 5;
    #pragma unroll
    for (int j = 0; j < 32; j += 8)
        t[ty + j][tx] = src[(size_t)(bk + ty + j) * Nd + bn + tx];
    __syncthreads();
    #pragma unroll
    for (int j = 0; j < 32; j += 8)
        dst[(size_t)(bn + ty + j) * PD + bk + tx] = __float2half(t[tx][ty + j]);
}

// ---------------------------------------------------------------------------
// QKV GEMM: 64x128 CTA tile, warp grid 2m x 4n (warp tile 32x32),
// 3 CTAs/SM. K=512 in 8 chunks, 3-stage cp.async pipeline (24KB/stage).
// bx: 0-3 Q, 4-7 K, 8-11 V. Epilogue -> g_q (scaled) / g_k / g_v.
// ---------------------------------------------------------------------------
__global__ void __launch_bounds__(256, 3)
gemm_qkv(const __half* __restrict__ Aq, const __half* __restrict__ Av,
         const __half* __restrict__ W, const float* __restrict__ normPtr)
{
    extern __shared__ char dsm[];
    uint32_t raw = smem_u32(dsm);
    uint32_t sb = (raw + 1023u) & ~1023u;

    const int tid = threadIdx.x, warp = tid >> 5, lane = tid & 31;
    const int wm = warp & 1, wn = warp >> 1;       // 2m x 4n
    const int lq = lane >> 2, lr = lane & 3;
    const int bx = blockIdx.x;
    const int m0 = blockIdx.y * 64;
    const int n0 = bx * 128;
    const int sector = bx >> 2;

    const __half* A = (sector == 0) ? Aq : Av;

    float acc[2][4][4];
    #pragma unroll
    for (int mi = 0; mi < 2; mi++)
        #pragma unroll
        for (int nj = 0; nj < 4; nj++)
            #pragma unroll
            for (int j = 0; j < 4; j++) acc[mi][nj][j] = 0.f;

    auto load_chunk = [&](int i) {
        const int k0 = i * 64;
        const uint32_t dA = sb + (i % 3) * 24576;
        const uint32_t dB = dA + 8192;
        #pragma unroll
        for (int l = 0; l < 2; l++) {
            int idx = tid + l * 256;
            int r = idx >> 3, c = (idx & 7) * 8;
            CP16(dA + SW128(r * 128 + c * 2), A + (size_t)(m0 + r) * PD + k0 + c);
        }
        #pragma unroll
        for (int l = 0; l < 4; l++) {
            int idx = tid + l * 256;
            int r = idx >> 3, c = (idx & 7) * 8;
            CP16(dB + SW128(r * 128 + c * 2), W + (size_t)(n0 + r) * PD + k0 + c);
        }
        CP_COMMIT();
    };

    load_chunk(0);
    load_chunk(1);

    #pragma unroll 1
    for (int i = 0; i < 8; i++) {
        if (i == 7) { CP_WAIT(0); }
        else        { CP_WAIT(1); }
        __syncthreads();
        if (i + 2 < 8) load_chunk(i + 2);  // buf (i+2)%3 == (i-1)%3: safe after sync

        const uint32_t Ab = sb + (i % 3) * 24576;
        const uint32_t Bb = Ab + 8192;
        #pragma unroll
        for (int ks = 0; ks < 4; ks++) {
            const int kh = ks * 16 + (lane >> 4) * 8;
            uint32_t a[2][4];
            #pragma unroll
            for (int mi = 0; mi < 2; mi++) {
                int row = wm * 32 + mi * 16 + (lane & 15);
                LDSM_X4(a[mi][0], a[mi][1], a[mi][2], a[mi][3],
                        Ab + SW128(row * 128 + kh * 2));
            }
            #pragma unroll
            for (int nj2 = 0; nj2 < 2; nj2++) {
                uint32_t r0, r1, r2, r3;
                int row = wn * 32 + nj2 * 16 + (lane & 15);
                LDSM_X4(r0, r1, r2, r3, Bb + SW128(row * 128 + kh * 2));
                #pragma unroll
                for (int mi = 0; mi < 2; mi++) {
                    mma_f16(acc[mi][2 * nj2],     a[mi][0], a[mi][1], a[mi][2], a[mi][3], r0, r2);
                    mma_f16(acc[mi][2 * nj2 + 1], a[mi][0], a[mi][1], a[mi][2], a[mi][3], r1, r3);
                }
            }
        }
    }

    // Epilogue: Q gets normalizer * log2(e) so flash can use exp2 directly
    const float scale = (sector == 0) ? (*normPtr * 1.4426950408889634f) : 1.f;
    __half* dst = (sector == 0) ? g_q : ((sector == 1) ? g_k : g_v);
    #pragma unroll
    for (int mi = 0; mi < 2; mi++)
        #pragma unroll
        for (int rr = 0; rr < 2; rr++) {
            int m = m0 + wm * 32 + mi * 16 + lq + rr * 8;
            int b = m >> 11, s = m & 2047;
            #pragma unroll
            for (int nj = 0; nj < 4; nj++) {
                int nn = (bx & 3) * 128 + wn * 32 + nj * 8 + 2 * lr;
                int h = nn >> 6, d = nn & 63;
                __half2 hv = __floats2half2_rn(acc[mi][nj][rr * 2] * scale,
                                               acc[mi][nj][rr * 2 + 1] * scale);
                *(__half2*)(dst + (((size_t)(b * PH + h)) * PS + s) * HD + d) = hv;
            }
        }
}

// ---------------------------------------------------------------------------
// Output GEMM: 128x128 CTA tile (256 CTAs = single wave), K=512 in 8 chunks,
// 3-stage cp.async pipeline, ldmatrix + m16n8k16 f32-acc. -> fp32 C.
// ---------------------------------------------------------------------------
__global__ void __launch_bounds__(256, 2)
gemm_out(const __half* __restrict__ Ain, const __half* __restrict__ W,
         float* __restrict__ C)
{
    extern __shared__ char dsm[];
    uint32_t raw = smem_u32(dsm);
    uint32_t sb = (raw + 1023u) & ~1023u;

    const int tid = threadIdx.x, warp = tid >> 5, lane = tid & 31;
    const int wm = warp & 3, wn = warp >> 2;
    const int lq = lane >> 2, lr = lane & 3;
    const int m0 = blockIdx.y * 128;
    const int n0 = blockIdx.x * 128;

    float acc[2][8][4];
    #pragma unroll
    for (int mi = 0; mi < 2; mi++)
        #pragma unroll
        for (int ni = 0; ni < 8; ni++)
            #pragma unroll
            for (int j = 0; j < 4; j++) acc[mi][ni][j] = 0.f;

    auto load_chunk = [&](int i) {
        const int k0 = i * 64;
        const uint32_t dA = sb + (i % 3) * 32768;
        const uint32_t dB = dA + 16384;
        #pragma unroll
        for (int l = 0; l < 4; l++) {
            int idx = tid + l * 256;
            int r = idx >> 3, c = (idx & 7) * 8;
            CP16(dA + SW128(r * 128 + c * 2), Ain + (size_t)(m0 + r) * PD + k0 + c);
            CP16(dB + SW128(r * 128 + c * 2), W + (size_t)(n0 + r) * PD + k0 + c);
        }
        CP_COMMIT();
    };

    load_chunk(0);
    load_chunk(1);

    #pragma unroll 1
    for (int i = 0; i < 8; i++) {
        if (i == 7) { CP_WAIT(0); }
        else        { CP_WAIT(1); }
        __syncthreads();
        if (i + 2 < 8) load_chunk(i + 2);

        const uint32_t Ab = sb + (i % 3) * 32768;
        const uint32_t Bb = Ab + 16384;
        #pragma unroll
        for (int ks = 0; ks < 4; ks++) {
            const int kh = ks * 16 + (lane >> 4) * 8;
            uint32_t a[2][4];
            #pragma unroll
            for (int mi = 0; mi < 2; mi++) {
                int row = wm * 32 + mi * 16 + (lane & 15);
                LDSM_X4(a[mi][0], a[mi][1], a[mi][2], a[mi][3],
                        Ab + SW128(row * 128 + kh * 2));
            }
            #pragma unroll
            for (int np = 0; np < 4; np++) {
                uint32_t r0, r1, r2, r3;
                int row = wn * 64 + np * 16 + (lane & 15);
                LDSM_X4(r0, r1, r2, r3, Bb + SW128(row * 128 + kh * 2));
                #pragma unroll
                for (int mi = 0; mi < 2; mi++) {
                    mma_f16(acc[mi][2 * np],     a[mi][0], a[mi][1], a[mi][2], a[mi][3], r0, r2);
                    mma_f16(acc[mi][2 * np + 1], a[mi][0], a[mi][1], a[mi][2], a[mi][3], r1, r3);
                }
            }
        }
    }

    #pragma unroll
    for (int mi = 0; mi < 2; mi++)
        #pragma unroll
        for (int rr = 0; rr < 2; rr++) {
            int m = m0 + wm * 32 + mi * 16 + lq + rr * 8;
            #pragma unroll
            for (int ni = 0; ni < 8; ni++) {
                int c = n0 + wn * 64 + ni * 8 + 2 * lr;
                *(float2*)(C + (size_t)m * PD + c) =
                    make_float2(acc[mi][ni][rr * 2], acc[mi][ni][rr * 2 + 1]);
            }
        }
}

// ---------------------------------------------------------------------------
// fp16 flash attention (validated best config): 128 q-rows, KV in 128-wide
// pairs, 8 warps, register-fused P, li via ones-column MMA, ballot-guarded
// alpha rescale, LPT grid (bh, qtile reversed). Causal.
// ---------------------------------------------------------------------------
__global__ void __launch_bounds__(256, 2)
flash_h()
{
    extern __shared__ char dsm[];
    uint32_t raw = smem_u32(dsm);
    uint32_t sb = (raw + 1023u) & ~1023u;
    const uint32_t Qs = sb;  // 16KB [r][d]
    // pair buffer b at sb+16384+b*32768: K(128 kv rows) 16KB, V 16KB

    const int bh = blockIdx.x;                            // 0..31
    const int qt = (int)gridDim.y - 1 - (int)blockIdx.y;  // heavy tiles first (LPT)
    const int qbase = qt * 128;

    const int tid = threadIdx.x, warp = tid >> 5, lane = tid & 31;
    const int lq = lane >> 2, lr = lane & 3;
    const int wrow = warp * 16;

    const __half* qp = g_q + (size_t)bh * PS * HD;
    const __half* kp = g_k + (size_t)bh * PS * HD;
    const __half* vp = g_v + (size_t)bh * PS * HD;

    auto load_pair = [&](int p) {   // loads K/V rows [p*128, p*128+128)
        const int kb = p * 128;
        const uint32_t base = sb + 16384 + (p & 1) * 32768;
        #pragma unroll
        for (int l = 0; l < 4; l++) {
            int idx = tid + l * 256;
            int r = idx >> 3, c = (idx & 7) * 8;
            CP16(base + SW128(r * 128 + c * 2),         kp + (size_t)(kb + r) * HD + c);
            CP16(base + 16384 + SW128(r * 128 + c * 2), vp + (size_t)(kb + r) * HD + c);
        }
        CP_COMMIT();
    };

    const int pairs = qt + 1;

    // Q tile + pair 0 in one commit group
    #pragma unroll
    for (int l = 0; l < 4; l++) {
        int idx = tid + l * 256;
        int r = idx >> 3, c = (idx & 7) * 8;
        CP16(Qs + SW128(r * 128 + c * 2), qp + (size_t)(qbase + r) * HD + c);
    }
    load_pair(0);

    CP_WAIT(0);
    __syncthreads();

    // Hoist Q fragments (warp-invariant across kv tiles): 16 regs
    uint32_t qf[4][4];
    #pragma unroll
    for (int ks = 0; ks < 4; ks++) {
        const int kh = ks * 16 + (lane >> 4) * 8;
        LDSM_X4(qf[ks][0], qf[ks][1], qf[ks][2], qf[ks][3],
                Qs + SW128((wrow + (lane & 15)) * 128 + kh * 2));
    }

    const uint32_t ONE2 = 0x3C003C00u;  // half2(1,1)
    float mi2[2] = {-1e30f, -1e30f};
    float lf[4] = {0.f, 0.f, 0.f, 0.f};   // li fragment (only lf[0], lf[2] consumed)
    float o[8][4];
    #pragma unroll
    for (int ni = 0; ni < 8; ni++)
        #pragma unroll
        for (int j = 0; j < 4; j++) o[ni][j] = 0.f;

    // one 64-kv sub-tile (kb = global kv base; Kb/Vb = smem bases, row-local)
    auto process_tile = [&](int kb, uint32_t Kb, uint32_t Vb) {
        // Skip warp-tiles entirely above the diagonal
        if (kb > qbase + wrow + 15) return;

        // ---- S = Q K^T ----
        float s[8][4];
        #pragma unroll
        for (int ni = 0; ni < 8; ni++)
            #pragma unroll
            for (int j = 0; j < 4; j++) s[ni][j] = 0.f;

        #pragma unroll
        for (int ks = 0; ks < 4; ks++) {
            const int kh = ks * 16 + (lane >> 4) * 8;
            #pragma unroll
            for (int np = 0; np < 4; np++) {
                uint32_t r0, r1, r2, r3;
                LDSM_X4(r0, r1, r2, r3,
                        Kb + SW128((np * 16 + (lane & 15)) * 128 + kh * 2));
                mma_f16(s[2 * np],     qf[ks][0], qf[ks][1], qf[ks][2], qf[ks][3], r0, r2);
                mma_f16(s[2 * np + 1], qf[ks][0], qf[ks][1], qf[ks][2], qf[ks][3], r1, r3);
            }
        }

        // Causal mask (only near the diagonal)
        if (kb + 63 > qbase + wrow) {
            #pragma unroll
            for (int ni = 0; ni < 8; ni++)
                #pragma unroll
                for (int j = 0; j < 4; j++) {
                    int col = kb + ni * 8 + 2 * lr + (j & 1);
                    int row = qbase + wrow + lq + ((j >> 1) << 3);
                    if (col > row) s[ni][j] = -1e30f;
                }
        }

        // Row max (fp32, quad reduce)
        float mn[2];
        #pragma unroll
        for (int rr = 0; rr < 2; rr++) {
            float mx = -1e30f;
            #pragma unroll
            for (int ni = 0; ni < 8; ni++)
                mx = fmaxf(mx, fmaxf(s[ni][rr * 2], s[ni][rr * 2 + 1]));
            mx = fmaxf(mx, __shfl_xor_sync(0xffffffffu, mx, 1));
            mx = fmaxf(mx, __shfl_xor_sync(0xffffffffu, mx, 2));
            mn[rr] = fmaxf(mi2[rr], mx);
        }

        // Ballot-guarded rescale: skipped only when alpha==1.0 exactly.
        bool adv = (mn[0] > mi2[0]) | (mn[1] > mi2[1]);
        if (__ballot_sync(0xffffffffu, adv)) {
            float a0 = fexp2(mi2[0] - mn[0]);
            float a1 = fexp2(mi2[1] - mn[1]);
            #pragma unroll
            for (int ni = 0; ni < 8; ni++) {
                o[ni][0] *= a0; o[ni][1] *= a0;
                o[ni][2] *= a1; o[ni][3] *= a1;
            }
            lf[0] *= a0;
            lf[2] *= a1;
            mi2[0] = mn[0];
            mi2[1] = mn[1];
        }

        // P = exp2(S - mn): subtract in fp32, convert, ex2.f16x2
        uint32_t ph[8][2];
        #pragma unroll
        for (int ni = 0; ni < 8; ni++) {
            __half2 h0 = __floats2half2_rn(s[ni][0] - mn[0], s[ni][1] - mn[0]);
            __half2 h1 = __floats2half2_rn(s[ni][2] - mn[1], s[ni][3] - mn[1]);
            ph[ni][0] = hexp2(*(uint32_t*)&h0);
            ph[ni][1] = hexp2(*(uint32_t*)&h1);
        }

        // li += P @ ones  (fp32 accumulate, cross-lane reduce inside mma)
        #pragma unroll
        for (int ks = 0; ks < 4; ks++)
            mma_f16(lf, ph[2 * ks][0], ph[2 * ks][1],
                    ph[2 * ks + 1][0], ph[2 * ks + 1][1], ONE2, ONE2);

        // ---- O += P V ----
        #pragma unroll
        for (int ks = 0; ks < 4; ks++) {
            #pragma unroll
            for (int dt = 0; dt < 4; dt++) {
                int kvr = ks * 16 + ((lane >> 3) & 1) * 8 + (lane & 7);
                int dof = dt * 16 + (lane >> 4) * 8;
                uint32_t r0, r1, r2, r3;
                LDSM_X4_T(r0, r1, r2, r3, Vb + SW128(kvr * 128 + dof * 2));
                mma_f16(o[dt * 2],     ph[2 * ks][0], ph[2 * ks][1],
                        ph[2 * ks + 1][0], ph[2 * ks + 1][1], r0, r1);
                mma_f16(o[dt * 2 + 1], ph[2 * ks][0], ph[2 * ks][1],
                        ph[2 * ks + 1][0], ph[2 * ks + 1][1], r2, r3);
            }
        }
    };

    #pragma unroll 1
    for (int p = 0; p < pairs; p++) {
        if (p > 0) {
            CP_WAIT(0);       // exactly pair p pending -> exact wait
            __syncthreads();
        }
        if (p + 1 < pairs) load_pair(p + 1);  // other buffer; in flight during processing

        const uint32_t base = sb + 16384 + (p & 1) * 32768;
        process_tile(p * 128,      base,        base + 16384);
        process_tile(p * 128 + 64, base + 8192, base + 16384 + 8192);
    }

    // Epilogue: g_heads[b][row][h*64+d] fp32
    const int b = bh >> 3, h = bh & 7;
    #pragma unroll
    for (int rr = 0; rr < 2; rr++) {
        float inv = 1.f / lf[rr * 2];
        int row = qbase + wrow + lq + rr * 8;
        #pragma unroll
        for (int ni = 0; ni < 8; ni++) {
            size_t off = ((size_t)b * PS + row) * PD + h * HD + ni * 8 + 2 * lr;
            *(float2*)(g_heads + off) =
                make_float2(o[ni][rr * 2] * inv, o[ni][rr * 2 + 1] * inv);
        }
    }
}

// ---------------------------------------------------------------------------
// Cross-head normalization (fp32 math, float2/thread)
// ---------------------------------------------------------------------------
__global__ void __launch_bounds__(256)
norm_k(const float* __restrict__ head_mults)
{
    int i = (blockIdx.x * 256 + threadIdx.x) * 2;  // over B*S*64, 2 hd/thread
    int hd = i & 63;
    int bs = i >> 6;
    size_t base = (size_t)bs * PD + hd;

    float2 v[PH];
    float2 mean = make_float2(0.f, 0.f);
    #pragma unroll
    for (int h = 0; h < PH; h++) {
        v[h] = *(const float2*)(g_heads + base + h * HD);
        mean.x += v[h].x; mean.y += v[h].y;
    }
    mean.x *= 0.125f; mean.y *= 0.125f;
    float2 var = make_float2(0.f, 0.f);
    #pragma unroll
    for (int h = 0; h < PH; h++) {
        float dx = v[h].x - mean.x, dy = v[h].y - mean.y;
        var.x += dx * dx; var.y += dy * dy;
    }
    float ix = 1.f / (sqrtf(var.x * 0.125f) + 0.01f);
    float iy = 1.f / (sqrtf(var.y * 0.125f) + 0.01f);
    #pragma unroll
    for (int h = 0; h < PH; h++) {
        float hm = head_mults[h];
        __half2 h0 = __floats2half2_rn((v[h].x - mean.x) * ix * hm,
                                       (v[h].y - mean.y) * iy * hm);
        *(uint32_t*)(g_normh + base + h * HD) = *(uint32_t*)&h0;
    }
}

// ---------------------------------------------------------------------------
// kernel_launch
// ---------------------------------------------------------------------------
extern "C" void kernel_launch(void* const* d_in, const int* in_sizes, int n_in,
                              void* d_out, int out_size)
{
    const float* query      = (const float*)d_in[0];
    const float* value      = (const float*)d_in[1];
    // d_in[2] = mask: pure causal additive mask, implemented analytically
    const float* Wq         = (const float*)d_in[3];
    const float* Wkv        = (const float*)d_in[4];
    const float* Wo         = (const float*)d_in[5];
    const float* normalizer = (const float*)d_in[6];
    const float* head_mults = (const float*)d_in[7];
    float* out = (float*)d_out;

    const int QKV_SMEM   = 3 * 24576 + 1024;          // 74752 -> 3 CTAs/SM
    const int OUT_SMEM   = 3 * 32768 + 1024;          // 99328 -> 2 CTAs/SM
    const int FLASH_SMEM = 16384 + 2 * 32768 + 1024;  // 83968 -> 2 CTAs/SM
    cudaFuncSetAttribute(gemm_qkv, cudaFuncAttributeMaxDynamicSharedMemorySize, QKV_SMEM);
    cudaFuncSetAttribute(gemm_out, cudaFuncAttributeMaxDynamicSharedMemorySize, OUT_SMEM);
    cudaFuncSetAttribute(flash_h,  cudaFuncAttributeMaxDynamicSharedMemorySize, FLASH_SMEM);

    __half *qin, *vin, *wT, *woT, *normh;
    cudaGetSymbolAddress((void**)&qin,   g_qin);
    cudaGetSymbolAddress((void**)&vin,   g_vin);
    cudaGetSymbolAddress((void**)&wT,    g_wT);
    cudaGetSymbolAddress((void**)&woT,   g_woT);
    cudaGetSymbolAddress((void**)&normh, g_normh);

    // 0. Fused prep: fp16 conversion of activations + weight transposes
    prep<<<2048 + 1024, 256>>>(query, value, Wq, Wkv, Wo);

    // 1. Fused QKV projection (64x128 tiles, 2m x 4n warps, 3 CTAs/SM)
    gemm_qkv<<<dim3(12, PM / 64), 256, QKV_SMEM>>>(qin, vin, wT, normalizer);

    // 2. Causal flash attention -> g_heads (fp32); grid (bh, qtile) = LPT order
    flash_h<<<dim3(BH, PS / 128), 256, FLASH_SMEM>>>();

    // 3. Cross-head normalization -> g_normh (fp16)
    norm_k<<<PB * PS * HD / 512, 256>>>(head_mults);

    // 4. Output projection -> d_out (fp32); 256 CTAs = single wave
    gemm_out<<<dim3(4, PM / 128), 256, OUT_SMEM>>>(normh, woT, out);
}